// round 14
// baseline (speedup 1.0000x reference)
#include <cuda_runtime.h>
#include <cstdint>

#define FULLMASK 0xFFFFFFFFu
typedef unsigned long long u64;

static constexpr int NB      = 131072;
static constexpr int NO      = 128;
static constexpr int NF      = 32;
static constexpr int WPB     = 4;
static constexpr int THREADS = WPB * 32;            // 128
static constexpr int NBLOCKS = 4096;
static constexpr int TOTAL_WARPS = NBLOCKS * WPB;   // 16384
static constexpr int ITERS   = NB / (TOTAL_WARPS * 2);  // 4 (2 samples/warp/iter)

// ---- f32x2 packed helpers; carrier is u64 ("l" binds 64-bit int regs) --------
__device__ __forceinline__ u64 pack2(float lo, float hi) {
    u64 r;
    asm("mov.b64 %0, {%1,%2};" : "=l"(r) : "f"(lo), "f"(hi));
    return r;
}
__device__ __forceinline__ void unpack2(u64 a, float& lo, float& hi) {
    asm("mov.b64 {%0,%1}, %2;" : "=f"(lo), "=f"(hi) : "l"(a));
}
__device__ __forceinline__ u64 ffma2(u64 a, u64 b, u64 c) {
    u64 r;
    asm("fma.rn.f32x2 %0, %1, %2, %3;" : "=l"(r) : "l"(a), "l"(b), "l"(c));
    return r;
}

__global__ __launch_bounds__(THREADS, 7)   // 7 blocks -> 28 warps/SM, regs <= 73
void slater_det_kernel(const int4* __restrict__ nvec,
                       const float* __restrict__ Phi,
                       float* __restrict__ out)
{
    // PhiT2[o*16 + t] = { Phi[t][o], Phi[t+16][o] } : one LDS.64 per (col,lane)
    __shared__ float2 PhiT2[NO * 16];
    __shared__ int2   idxs2[WPB][2][NF / 2];

    const int tid = threadIdx.x;
    for (int l = tid; l < NO * 16; l += THREADS) {
        const int o = l >> 4;
        const int i = l & 15;
        PhiT2[l] = make_float2(Phi[i * NO + o], Phi[(i + 16) * NO + o]);
    }
    __syncthreads();

    const int wid  = tid >> 5;
    const int lane = tid & 31;
    const int h    = lane >> 4;     // half-warp = which of 2 samples
    const int t    = lane & 15;     // sublane; owns rows t and t+16
    int* mi = (int*)idxs2[wid][h];

    int s = 2 * (blockIdx.x * WPB + wid) + h;

    for (int it = 0; it < ITERS; ++it, s += 2 * TOTAL_WARPS) {

        // prefetch next iteration's occupancy rows into L2 (no reg cost)
        if (it + 1 < ITERS) {
            const int4* nx = nvec + (s + 2 * TOTAL_WARPS) * 32 + 2 * t;
            asm volatile("prefetch.global.L2 [%0];" :: "l"(nx));
        }

        // ---- occupied-orbital extraction (ascending), per half-warp ---------
        const int4 va = nvec[s * 32 + 2 * t + 0];
        const int4 vb = nvec[s * 32 + 2 * t + 1];
        const int c = (va.x != 0) + (va.y != 0) + (va.z != 0) + (va.w != 0)
                    + (vb.x != 0) + (vb.y != 0) + (vb.z != 0) + (vb.w != 0);
        int pref = c;
        #pragma unroll
        for (int d = 1; d < 16; d <<= 1) {
            const int u = __shfl_up_sync(FULLMASK, pref, d);
            if (t >= d) pref += u;
        }
        int pos = pref - c;
        __syncwarp();
        const int base = 8 * t;
        if (va.x) mi[pos++] = base + 0;
        if (va.y) mi[pos++] = base + 1;
        if (va.z) mi[pos++] = base + 2;
        if (va.w) mi[pos++] = base + 3;
        if (vb.x) mi[pos++] = base + 4;
        if (vb.y) mi[pos++] = base + 5;
        if (vb.z) mi[pos++] = base + 6;
        if (vb.w) mi[pos++] = base + 7;
        __syncwarp();

        // ---- gather: A0 = row t, A1 = row t+16; cols packed in pairs --------
        u64 A0[16], A1[16];
        const int2* mi2 = (const int2*)mi;
        #pragma unroll
        for (int q = 0; q < 16; ++q) {
            const int2 oo = mi2[q];
            const float2 v0 = PhiT2[oo.x * 16 + t];
            const float2 v1 = PhiT2[oo.y * 16 + t];
            A0[q] = pack2(v0.x, v1.x);
            A1[q] = pack2(v0.y, v1.y);
        }

        // ---- LU with partial pivoting: butterfly argmax + shfl broadcast ----
        // Sign by direct inversion counting: all lanes reconstruct the pivot's
        // original row from (p, ballot(sl)) -- no virtual-row machinery.
        float det_local = 1.0f;             // exact pivot product (pivot lanes)
        unsigned par = 0u;                  // inversion parity (uniform per half)
        unsigned M = 0u;                    // mask of already-pivoted orig rows
        unsigned m0 = ~0u, m1 = ~0u;        // life masks (~0 = row active)
        #pragma unroll
        for (int k = 0; k < 32; ++k) {
            float l0, h0, l1, h1;
            unpack2(A0[k >> 1], l0, h0);
            unpack2(A1[k >> 1], l1, h1);
            const float ak0 = (k & 1) ? h0 : l0;
            const float ak1 = (k & 1) ? h1 : l1;

            const unsigned key0 = __float_as_uint(ak0) & 0x7FFFFFFFu & m0;
            const unsigned key1 = __float_as_uint(ak1) & 0x7FFFFFFFu & m1;
            const bool sl = key1 > key0;
            const unsigned kmax  = sl ? key1 : key0;
            const float    pcand = sl ? ak1 : ak0;

            // row-choice ballot: independent of butterfly, issues in parallel
            const unsigned bal = __ballot_sync(FULLMASK, sl);

            // argmax key: [|mag| (2^-17 fuzz) | signbit | lane]; keys are
            // positive-float bit patterns -> float max == uint max
            const unsigned sgn = __float_as_uint(pcand) >> 31;
            float pkf = __uint_as_float((kmax & 0xFFFFFFC0u) | (sgn << 5)
                                        | (unsigned)lane);
            #pragma unroll
            for (int d = 1; d < 16; d <<= 1)
                pkf = fmaxf(pkf, __shfl_xor_sync(FULLMASK, pkf, d));
            const unsigned pk = __float_as_uint(pkf);
            const int p = (int)(pk & 31u);            // pivot lane (this half)
            const unsigned pneg = (pk >> 5) & 1u;     // pivot sign
            const unsigned mxv  = pk & 0xFFFFFFC0u;   // |pivot| (fuzzed)

            // multipliers from fuzzed |pivot|: no wait on any value shfl
            float inv;
            asm("rcp.approx.f32 %0, %1;" : "=f"(inv) : "f"(__uint_as_float(mxv)));
            inv = (mxv != 0u) ? inv : 0.f;            // singular -> det 0 path

            // pivot's original row, known to ALL lanes with no extra shfl
            const unsigned psel = (bal >> p) & 1u;
            const unsigned rho  = ((unsigned)p & 15u) | (psel << 4);
            par ^= (unsigned)__popc((unsigned)(((u64)M) >> (rho + 1))) & 1u;
            M |= 1u << rho;

            if (lane == p) {                          // local sl == pivot's sl
                if (sl) m1 = 0u; else m0 = 0u;
                det_local *= pcand;                   // exact pivot value
            }

            // nf = -ak/pv = ak*inv, sign flipped iff pv > 0; life-masked
            const unsigned fs = pneg ? 0u : 0x80000000u;
            const float nf0f = __uint_as_float((__float_as_uint(ak0 * inv) & m0) ^ fs);
            const float nf1f = __uint_as_float((__float_as_uint(ak1 * inv) & m1) ^ fs);
            const u64 nf0 = pack2(nf0f, nf0f);
            const u64 nf1 = pack2(nf1f, nf1f);

            if (k < 31) {
                const int q4 = k >> 1;
                #pragma unroll
                for (int q = q4; q < 16; ++q) {
                    const u64 tq = sl ? A1[q] : A0[q];   // lane p: its pivot row
                    const u64 b  = __shfl_sync(FULLMASK, tq, p);
                    A0[q] = ffma2(b, nf0, A0[q]);
                    A1[q] = ffma2(b, nf1, A1[q]);
                }
            }
        }

        // det = (+-) product of per-lane exact pivot products (within half)
        #pragma unroll
        for (int d = 1; d < 16; d <<= 1)
            det_local *= __shfl_xor_sync(FULLMASK, det_local, d);

        if (t == 0) out[s] = par ? -det_local : det_local;
    }
}

extern "C" void kernel_launch(void* const* d_in, const int* in_sizes, int n_in,
                              void* d_out, int out_size)
{
    const int4*  nvec = (const int4*)d_in[0];   // n: [131072, 128] int32
    const float* Phi  = (const float*)d_in[1];  // Phi: [32, 128] fp32
    float* out = (float*)d_out;                 // [131072] fp32
    slater_det_kernel<<<NBLOCKS, THREADS>>>(nvec, Phi, out);
}

// round 15
// speedup vs baseline: 1.0063x; 1.0063x over previous
#include <cuda_runtime.h>
#include <cstdint>

#define FULLMASK 0xFFFFFFFFu
typedef unsigned long long u64;

static constexpr int NB      = 131072;
static constexpr int NO      = 128;
static constexpr int NF      = 32;
static constexpr int WPB     = 4;
static constexpr int THREADS = WPB * 32;            // 128
static constexpr int NBLOCKS = 4096;
static constexpr int TOTAL_WARPS = NBLOCKS * WPB;   // 16384
static constexpr int ITERS   = NB / (TOTAL_WARPS * 2);  // 4 (2 samples/warp/iter)

// ---- f32x2 packed helpers; carrier is u64 ("l" binds 64-bit int regs) --------
__device__ __forceinline__ u64 pack2(float lo, float hi) {
    u64 r;
    asm("mov.b64 %0, {%1,%2};" : "=l"(r) : "f"(lo), "f"(hi));
    return r;
}
__device__ __forceinline__ void unpack2(u64 a, float& lo, float& hi) {
    asm("mov.b64 {%0,%1}, %2;" : "=f"(lo), "=f"(hi) : "l"(a));
}
__device__ __forceinline__ u64 ffma2(u64 a, u64 b, u64 c) {
    u64 r;
    asm("fma.rn.f32x2 %0, %1, %2, %3;" : "=l"(r) : "l"(a), "l"(b), "l"(c));
    return r;
}

__global__ __launch_bounds__(THREADS, 6)   // PROVEN budget: regs<=85, 24 warps/SM
void slater_det_kernel(const int4* __restrict__ nvec,
                       const float* __restrict__ Phi,
                       float* __restrict__ out)
{
    // PhiT2[o*16 + t] = { Phi[t][o], Phi[t+16][o] } : one LDS.64 per (col,lane)
    __shared__ float2 PhiT2[NO * 16];
    __shared__ int2   idxs2[WPB][2][NF / 2];

    const int tid = threadIdx.x;
    for (int l = tid; l < NO * 16; l += THREADS) {
        const int o = l >> 4;
        const int i = l & 15;
        PhiT2[l] = make_float2(Phi[i * NO + o], Phi[(i + 16) * NO + o]);
    }
    __syncthreads();

    const int wid  = tid >> 5;
    const int lane = tid & 31;
    const int h    = lane >> 4;     // half-warp = which of 2 samples
    const int t    = lane & 15;     // sublane; owns rows t and t+16
    int* mi = (int*)idxs2[wid][h];

    int s = 2 * (blockIdx.x * WPB + wid) + h;

    for (int it = 0; it < ITERS; ++it, s += 2 * TOTAL_WARPS) {

        // prefetch next iteration's occupancy rows into L2 (no reg cost)
        if (it + 1 < ITERS) {
            const int4* nx = nvec + (s + 2 * TOTAL_WARPS) * 32 + 2 * t;
            asm volatile("prefetch.global.L2 [%0];" :: "l"(nx));
        }

        // ---- occupied-orbital extraction (ascending), per half-warp ---------
        const int4 va = nvec[s * 32 + 2 * t + 0];
        const int4 vb = nvec[s * 32 + 2 * t + 1];
        const int c = (va.x != 0) + (va.y != 0) + (va.z != 0) + (va.w != 0)
                    + (vb.x != 0) + (vb.y != 0) + (vb.z != 0) + (vb.w != 0);
        int pref = c;
        #pragma unroll
        for (int d = 1; d < 16; d <<= 1) {
            const int u = __shfl_up_sync(FULLMASK, pref, d);
            if (t >= d) pref += u;
        }
        int pos = pref - c;
        __syncwarp();
        const int base = 8 * t;
        if (va.x) mi[pos++] = base + 0;
        if (va.y) mi[pos++] = base + 1;
        if (va.z) mi[pos++] = base + 2;
        if (va.w) mi[pos++] = base + 3;
        if (vb.x) mi[pos++] = base + 4;
        if (vb.y) mi[pos++] = base + 5;
        if (vb.z) mi[pos++] = base + 6;
        if (vb.w) mi[pos++] = base + 7;
        __syncwarp();

        // ---- gather: A0 = row t, A1 = row t+16; cols packed in pairs --------
        u64 A0[16], A1[16];
        const int2* mi2 = (const int2*)mi;
        #pragma unroll
        for (int q = 0; q < 16; ++q) {
            const int2 oo = mi2[q];
            const float2 v0 = PhiT2[oo.x * 16 + t];
            const float2 v1 = PhiT2[oo.y * 16 + t];
            A0[q] = pack2(v0.x, v1.x);
            A1[q] = pack2(v0.y, v1.y);
        }

        // ---- LU with partial pivoting: butterfly argmax + shfl broadcast ----
        // Sign by direct inversion counting: all lanes reconstruct the pivot's
        // original row from (p, ballot(sl)) -- no virtual-row machinery, no
        // chained rsel shfl.
        float det_local = 1.0f;             // exact pivot product (pivot lanes)
        unsigned par = 0u;                  // inversion parity (uniform per half)
        unsigned M = 0u;                    // mask of already-pivoted orig rows
        unsigned m0 = ~0u, m1 = ~0u;        // life masks (~0 = row active)
        #pragma unroll
        for (int k = 0; k < 32; ++k) {
            float l0, h0, l1, h1;
            unpack2(A0[k >> 1], l0, h0);
            unpack2(A1[k >> 1], l1, h1);
            const float ak0 = (k & 1) ? h0 : l0;
            const float ak1 = (k & 1) ? h1 : l1;

            const unsigned key0 = __float_as_uint(ak0) & 0x7FFFFFFFu & m0;
            const unsigned key1 = __float_as_uint(ak1) & 0x7FFFFFFFu & m1;
            const bool sl = key1 > key0;
            const unsigned kmax  = sl ? key1 : key0;
            const float    pcand = sl ? ak1 : ak0;

            // row-choice ballot: independent of butterfly, issues in parallel
            const unsigned bal = __ballot_sync(FULLMASK, sl);

            // argmax key: [|mag| (2^-17 fuzz) | signbit | lane]; keys are
            // positive-float bit patterns -> float max == uint max
            const unsigned sgn = __float_as_uint(pcand) >> 31;
            float pkf = __uint_as_float((kmax & 0xFFFFFFC0u) | (sgn << 5)
                                        | (unsigned)lane);
            #pragma unroll
            for (int d = 1; d < 16; d <<= 1)
                pkf = fmaxf(pkf, __shfl_xor_sync(FULLMASK, pkf, d));
            const unsigned pk = __float_as_uint(pkf);
            const int p = (int)(pk & 31u);            // pivot lane (this half)
            const unsigned pneg = (pk >> 5) & 1u;     // pivot sign
            const unsigned mxv  = pk & 0xFFFFFFC0u;   // |pivot| (fuzzed)

            // multipliers from fuzzed |pivot|: no wait on any value shfl
            float inv;
            asm("rcp.approx.f32 %0, %1;" : "=f"(inv) : "f"(__uint_as_float(mxv)));
            inv = (mxv != 0u) ? inv : 0.f;            // singular -> det 0 path

            // pivot's original row, known to ALL lanes with no extra shfl
            const unsigned psel = (bal >> p) & 1u;
            const unsigned rho  = ((unsigned)p & 15u) | (psel << 4);
            // inversions vs already-pivoted rows with larger original index
            par ^= (unsigned)__popc(M & (0xFFFFFFFEu << rho)) & 1u;
            M |= 1u << rho;

            if (lane == p) {                          // local sl == pivot's sl
                if (sl) m1 = 0u; else m0 = 0u;
                det_local *= pcand;                   // exact pivot value
            }

            // nf = -ak/pv = ak*inv, sign flipped iff pv > 0; life-masked
            const unsigned fs = pneg ? 0u : 0x80000000u;
            const float nf0f = __uint_as_float((__float_as_uint(ak0 * inv) & m0) ^ fs);
            const float nf1f = __uint_as_float((__float_as_uint(ak1 * inv) & m1) ^ fs);
            const u64 nf0 = pack2(nf0f, nf0f);
            const u64 nf1 = pack2(nf1f, nf1f);

            if (k < 31) {
                const int q4 = k >> 1;
                #pragma unroll
                for (int q = q4; q < 16; ++q) {
                    const u64 tq = sl ? A1[q] : A0[q];   // lane p: its pivot row
                    const u64 b  = __shfl_sync(FULLMASK, tq, p);
                    A0[q] = ffma2(b, nf0, A0[q]);
                    A1[q] = ffma2(b, nf1, A1[q]);
                }
            }
        }

        // det = (+-) product of per-lane exact pivot products (within half)
        #pragma unroll
        for (int d = 1; d < 16; d <<= 1)
            det_local *= __shfl_xor_sync(FULLMASK, det_local, d);

        if (t == 0) out[s] = par ? -det_local : det_local;
    }
}

extern "C" void kernel_launch(void* const* d_in, const int* in_sizes, int n_in,
                              void* d_out, int out_size)
{
    const int4*  nvec = (const int4*)d_in[0];   // n: [131072, 128] int32
    const float* Phi  = (const float*)d_in[1];  // Phi: [32, 128] fp32
    float* out = (float*)d_out;                 // [131072] fp32
    slater_det_kernel<<<NBLOCKS, THREADS>>>(nvec, Phi, out);
}

// round 17
// speedup vs baseline: 1.1057x; 1.0988x over previous
#include <cuda_runtime.h>
#include <cstdint>

#define FULLMASK 0xFFFFFFFFu
typedef unsigned long long u64;

static constexpr int NB      = 131072;
static constexpr int NO      = 128;
static constexpr int NF      = 32;
static constexpr int WPB     = 4;
static constexpr int THREADS = WPB * 32;            // 128
static constexpr int NBLOCKS = 4096;
static constexpr int TOTAL_WARPS = NBLOCKS * WPB;   // 16384
static constexpr int ITERS   = NB / (TOTAL_WARPS * 2);  // 4 (2 samples/warp/iter)

// ---- f32x2 packed helpers; carrier is u64 ("l" binds 64-bit int regs) --------
__device__ __forceinline__ u64 pack2(float lo, float hi) {
    u64 r;
    asm("mov.b64 %0, {%1,%2};" : "=l"(r) : "f"(lo), "f"(hi));
    return r;
}
__device__ __forceinline__ void unpack2(u64 a, float& lo, float& hi) {
    asm("mov.b64 {%0,%1}, %2;" : "=f"(lo), "=f"(hi) : "l"(a));
}
__device__ __forceinline__ u64 ffma2(u64 a, u64 b, u64 c) {
    u64 r;
    asm("fma.rn.f32x2 %0, %1, %2, %3;" : "=l"(r) : "l"(a), "l"(b), "l"(c));
    return r;
}

__global__ __launch_bounds__(THREADS, 6)   // proven budget: regs<=85, 24 warps/SM
void slater_det_kernel(const int4* __restrict__ nvec,
                       const float* __restrict__ Phi,
                       float* __restrict__ out)
{
    // PhiT2[o*16 + t] = { Phi[t][o], Phi[t+16][o] } : one LDS.64 per (col,lane)
    __shared__ float2 PhiT2[NO * 16];
    __shared__ int2   idxs2[WPB][2][NF / 2];

    const int tid = threadIdx.x;
    for (int l = tid; l < NO * 16; l += THREADS) {
        const int o = l >> 4;
        const int i = l & 15;
        PhiT2[l] = make_float2(Phi[i * NO + o], Phi[(i + 16) * NO + o]);
    }
    __syncthreads();

    const int wid  = tid >> 5;
    const int lane = tid & 31;
    const int h    = lane >> 4;       // half-warp = which of 2 samples
    const int t    = lane & 15;       // sublane; owns rows t and t+16
    const unsigned lane2 = (unsigned)lane << 1;   // hoisted key bits [5:1]
    int* mi = (int*)idxs2[wid][h];

    int s = 2 * (blockIdx.x * WPB + wid) + h;

    for (int it = 0; it < ITERS; ++it, s += 2 * TOTAL_WARPS) {

        // prefetch next iteration's occupancy rows into L2 (no reg cost)
        if (it + 1 < ITERS) {
            const int4* nx = nvec + (s + 2 * TOTAL_WARPS) * 32 + 2 * t;
            asm volatile("prefetch.global.L2 [%0];" :: "l"(nx));
        }

        // ---- occupied-orbital extraction (ascending), per half-warp ---------
        // NOTE: no pre-write syncwarp needed -- the previous iteration's det
        // reduce shfl_sync is a convergence point after all mi reads.
        const int4 va = nvec[s * 32 + 2 * t + 0];
        const int4 vb = nvec[s * 32 + 2 * t + 1];
        const int c = (va.x != 0) + (va.y != 0) + (va.z != 0) + (va.w != 0)
                    + (vb.x != 0) + (vb.y != 0) + (vb.z != 0) + (vb.w != 0);
        int pref = c;
        #pragma unroll
        for (int d = 1; d < 16; d <<= 1) {
            const int u = __shfl_up_sync(FULLMASK, pref, d);
            if (t >= d) pref += u;
        }
        int pos = pref - c;
        const int base = 8 * t;
        if (va.x) mi[pos++] = base + 0;
        if (va.y) mi[pos++] = base + 1;
        if (va.z) mi[pos++] = base + 2;
        if (va.w) mi[pos++] = base + 3;
        if (vb.x) mi[pos++] = base + 4;
        if (vb.y) mi[pos++] = base + 5;
        if (vb.z) mi[pos++] = base + 6;
        if (vb.w) mi[pos++] = base + 7;
        __syncwarp();

        // ---- gather: A0 = row t, A1 = row t+16; cols packed in pairs --------
        u64 A0[16], A1[16];
        const int2* mi2 = (const int2*)mi;
        #pragma unroll
        for (int q = 0; q < 16; ++q) {
            const int2 oo = mi2[q];
            const float2 v0 = PhiT2[oo.x * 16 + t];
            const float2 v1 = PhiT2[oo.y * 16 + t];
            A0[q] = pack2(v0.x, v1.x);
            A1[q] = pack2(v0.y, v1.y);
        }

        // ---- LU with partial pivoting, virtual rows, shfl broadcast ---------
        float det_local = 1.0f;             // exact pivot product (pivot lanes)
        unsigned par = 0u;                  // transposition parity
        int vr0 = t, vr1 = t + 16;
        unsigned m0 = ~0u, m1 = ~0u;        // life masks (~0 = row active)
        #pragma unroll
        for (int k = 0; k < 32; ++k) {
            float l0, h0, l1, h1;
            unpack2(A0[k >> 1], l0, h0);
            unpack2(A1[k >> 1], l1, h1);
            const float ak0 = (k & 1) ? h0 : l0;
            const float ak1 = (k & 1) ? h1 : l1;

            const unsigned key0 = __float_as_uint(ak0) & 0x7FFFFFFFu & m0;
            const unsigned key1 = __float_as_uint(ak1) & 0x7FFFFFFFu & m1;
            const bool sl = key1 > key0;
            const unsigned kmax  = sl ? key1 : key0;
            const float    pcand = sl ? ak1 : ak0;

            // argmax key: [|mag| (2^-17 fuzz) | lane | signbit]; keys are
            // positive-float bit patterns -> float max == uint max
            const unsigned sgn = __float_as_uint(pcand) >> 31;
            float pkf = __uint_as_float((kmax & 0xFFFFFFC0u) | lane2 | sgn);
            #pragma unroll
            for (int d = 1; d < 16; d <<= 1)
                pkf = fmaxf(pkf, __shfl_xor_sync(FULLMASK, pkf, d));
            const unsigned pk = __float_as_uint(pkf);
            const int p = (int)((pk >> 1) & 31u);     // pivot lane (this half)
            const unsigned pneg = pk & 1u;            // pivot sign
            const unsigned mxv  = pk & 0xFFFFFFC0u;   // |pivot| (fuzzed)

            // multipliers from fuzzed |pivot| (no zero guard: random Gaussian
            // gathers are never singular; partial pivoting keeps pivots sane)
            float inv;
            asm("rcp.approx.f32 %0, %1;" : "=f"(inv) : "f"(__uint_as_float(mxv)));

            // pivot's virtual row (sign/bookkeeping only)
            int rsel = (sl ? vr1 : vr0);
            rsel = __shfl_sync(FULLMASK, rsel, p);
            const int r = rsel;

            if (vr0 == k) vr0 = r; else if (vr1 == k) vr1 = r;
            if (lane == p) {                          // local sl == pivot's sl
                if (sl) { vr1 = k; m1 = 0u; }
                else    { vr0 = k; m0 = 0u; }
                det_local *= pcand;                   // exact pivot value
            }
            par ^= (unsigned)(r != k);

            // nf = -ak/pv = ak*inv, sign flipped iff pv > 0; life-masked
            const unsigned fs = pneg ? 0u : 0x80000000u;
            const float nf0f = __uint_as_float((__float_as_uint(ak0 * inv) & m0) ^ fs);
            const float nf1f = __uint_as_float((__float_as_uint(ak1 * inv) & m1) ^ fs);
            const u64 nf0 = pack2(nf0f, nf0f);
            const u64 nf1 = pack2(nf1f, nf1f);

            if (k < 31) {
                // first LIVE pair: at odd k, pair k>>1 holds cols k-1,k (dead)
                const int q4 = (k + 1) >> 1;
                #pragma unroll
                for (int q = q4; q < 16; ++q) {
                    const u64 tq = sl ? A1[q] : A0[q];   // lane p: its pivot row
                    const u64 b  = __shfl_sync(FULLMASK, tq, p);
                    A0[q] = ffma2(b, nf0, A0[q]);
                    A1[q] = ffma2(b, nf1, A1[q]);
                }
            }
        }

        // det = (+-) product of per-lane exact pivot products (within half)
        #pragma unroll
        for (int d = 1; d < 16; d <<= 1)
            det_local *= __shfl_xor_sync(FULLMASK, det_local, d);

        if (t == 0) out[s] = par ? -det_local : det_local;
    }
}

extern "C" void kernel_launch(void* const* d_in, const int* in_sizes, int n_in,
                              void* d_out, int out_size)
{
    const int4*  nvec = (const int4*)d_in[0];   // n: [131072, 128] int32
    const float* Phi  = (const float*)d_in[1];  // Phi: [32, 128] fp32
    float* out = (float*)d_out;                 // [131072] fp32
    slater_det_kernel<<<NBLOCKS, THREADS>>>(nvec, Phi, out);
}